// round 1
// baseline (speedup 1.0000x reference)
#include <cuda_runtime.h>
#include <cuda_bf16.h>
#include <math.h>

// Problem constants
#define S_LEN 2048
#define HID   1024
#define NH    8
#define DK    128
#define DV    128
#define KCONV 4
#define SCALE 0.08838834764831845f   // 128^-0.5
#define EPS   1e-5f

// ---------------------------------------------------------------------------
// Static device scratch (no allocation allowed)
// ---------------------------------------------------------------------------
__device__ float g_qb[S_LEN * HID];   // x@Wq^T (pre-conv)
__device__ float g_kb[S_LEN * HID];
__device__ float g_vb[S_LEN * HID];
__device__ float g_qc[S_LEN * HID];   // post conv+silu
__device__ float g_kc[S_LEN * HID];
__device__ float g_vc[S_LEN * HID];
__device__ float g_gb[S_LEN * HID];   // x@Wg^T (pre-sigmoid)
__device__ float g_ob[S_LEN * HID];   // recurrence output o[t,h,v]
__device__ float g_o2[S_LEN * HID];   // post LN*gate
__device__ float g_alpha[S_LEN * NH];
__device__ float g_beta [S_LEN * NH];

// ---------------------------------------------------------------------------
// SGEMM: C[M,N] = A[M,K] * B[N,K]^T   (A row-major, B row-major [N,K])
// 128x128 block tile, 8x8 microtile, K-chunk 8, double-buffered smem.
// Requires M%128==0, N%128==0, K%8==0, K%4==0 alignment (true here).
// ---------------------------------------------------------------------------
__global__ __launch_bounds__(256) void sgemm_tn(const float* __restrict__ A,
                                                const float* __restrict__ B,
                                                float* __restrict__ C,
                                                int M, int N, int K) {
    __shared__ float As[2][8][128];
    __shared__ float Bs[2][8][128];

    const int tid = threadIdx.x;
    const int bm = blockIdx.y * 128;
    const int bn = blockIdx.x * 128;

    // global load indices: each thread loads one float4 of A and one of B per chunk
    const int lr = tid >> 1;          // 0..127 row within tile
    const int lc = (tid & 1) * 4;     // 0 or 4 col within 8-chunk

    // compute indices
    const int tx = tid & 15;          // 0..15  -> N subtile
    const int ty = tid >> 4;          // 0..15  -> M subtile

    float acc[8][8];
#pragma unroll
    for (int i = 0; i < 8; i++)
#pragma unroll
        for (int j = 0; j < 8; j++) acc[i][j] = 0.f;

    // preload chunk 0
    float4 av = *reinterpret_cast<const float4*>(&A[(size_t)(bm + lr) * K + lc]);
    float4 bv = *reinterpret_cast<const float4*>(&B[(size_t)(bn + lr) * K + lc]);
    As[0][lc + 0][lr] = av.x; As[0][lc + 1][lr] = av.y;
    As[0][lc + 2][lr] = av.z; As[0][lc + 3][lr] = av.w;
    Bs[0][lc + 0][lr] = bv.x; Bs[0][lc + 1][lr] = bv.y;
    Bs[0][lc + 2][lr] = bv.z; Bs[0][lc + 3][lr] = bv.w;
    __syncthreads();

    for (int kt = 0; kt < K; kt += 8) {
        const int cur = (kt >> 3) & 1;
        const int nxt = cur ^ 1;
        float4 an, bn4;
        const bool has_next = (kt + 8) < K;
        if (has_next) {
            an  = *reinterpret_cast<const float4*>(&A[(size_t)(bm + lr) * K + kt + 8 + lc]);
            bn4 = *reinterpret_cast<const float4*>(&B[(size_t)(bn + lr) * K + kt + 8 + lc]);
        }
#pragma unroll
        for (int kk = 0; kk < 8; kk++) {
            float4 a0 = *reinterpret_cast<const float4*>(&As[cur][kk][ty * 8]);
            float4 a1 = *reinterpret_cast<const float4*>(&As[cur][kk][ty * 8 + 4]);
            float4 b0 = *reinterpret_cast<const float4*>(&Bs[cur][kk][tx * 8]);
            float4 b1 = *reinterpret_cast<const float4*>(&Bs[cur][kk][tx * 8 + 4]);
            float ar[8] = {a0.x, a0.y, a0.z, a0.w, a1.x, a1.y, a1.z, a1.w};
            float br[8] = {b0.x, b0.y, b0.z, b0.w, b1.x, b1.y, b1.z, b1.w};
#pragma unroll
            for (int i = 0; i < 8; i++)
#pragma unroll
                for (int j = 0; j < 8; j++) acc[i][j] = fmaf(ar[i], br[j], acc[i][j]);
        }
        if (has_next) {
            As[nxt][lc + 0][lr] = an.x;  As[nxt][lc + 1][lr] = an.y;
            As[nxt][lc + 2][lr] = an.z;  As[nxt][lc + 3][lr] = an.w;
            Bs[nxt][lc + 0][lr] = bn4.x; Bs[nxt][lc + 1][lr] = bn4.y;
            Bs[nxt][lc + 2][lr] = bn4.z; Bs[nxt][lc + 3][lr] = bn4.w;
            __syncthreads();
        }
    }

#pragma unroll
    for (int i = 0; i < 8; i++) {
        const size_t row = (size_t)(bm + ty * 8 + i) * N + bn + tx * 8;
        float4 c0 = make_float4(acc[i][0], acc[i][1], acc[i][2], acc[i][3]);
        float4 c1 = make_float4(acc[i][4], acc[i][5], acc[i][6], acc[i][7]);
        *reinterpret_cast<float4*>(&C[row])     = c0;
        *reinterpret_cast<float4*>(&C[row + 4]) = c1;
    }
}

// ---------------------------------------------------------------------------
// alpha/beta projections: alpha[t,h] = sigmoid(x_t . Wa_h + ba_h), same beta.
// One block per t, 8 warps: warp h does both dots.
// ---------------------------------------------------------------------------
__global__ __launch_bounds__(256) void ab_kernel(const float* __restrict__ x,
                                                 const float* __restrict__ Wa,
                                                 const float* __restrict__ ba,
                                                 const float* __restrict__ Wb,
                                                 const float* __restrict__ bb,
                                                 float* __restrict__ alpha,
                                                 float* __restrict__ beta) {
    const int t = blockIdx.x;
    const int w = threadIdx.x >> 5;   // head
    const int lane = threadIdx.x & 31;
    const float* xr = x + (size_t)t * HID;
    const float* war = Wa + (size_t)w * HID;
    const float* wbr = Wb + (size_t)w * HID;
    float sa = 0.f, sb = 0.f;
    for (int i = lane; i < HID; i += 32) {
        float xv = xr[i];
        sa = fmaf(xv, war[i], sa);
        sb = fmaf(xv, wbr[i], sb);
    }
#pragma unroll
    for (int off = 16; off > 0; off >>= 1) {
        sa += __shfl_down_sync(0xffffffffu, sa, off);
        sb += __shfl_down_sync(0xffffffffu, sb, off);
    }
    if (lane == 0) {
        alpha[t * NH + w] = 1.f / (1.f + expf(-(sa + ba[w])));
        beta [t * NH + w] = 1.f / (1.f + expf(-(sb + bb[w])));
    }
}

// ---------------------------------------------------------------------------
// Depthwise causal conv (K=4) + bias + SiLU (+ optional scale for K path)
// ---------------------------------------------------------------------------
__global__ __launch_bounds__(256) void conv_silu(const float* __restrict__ in,
                                                 const float* __restrict__ w,
                                                 const float* __restrict__ b,
                                                 float* __restrict__ out,
                                                 float scale) {
    const int idx = blockIdx.x * 256 + threadIdx.x;  // over S*HID
    const int t = idx >> 10;
    const int c = idx & 1023;
    float acc = b[c];
#pragma unroll
    for (int j = 0; j < KCONV; j++) {
        const int tt = t + j - (KCONV - 1);
        if (tt >= 0) acc = fmaf(in[((size_t)tt << 10) + c], w[c * KCONV + j], acc);
    }
    const float sil = acc / (1.f + expf(-acc));
    out[idx] = sil * scale;
}

// ---------------------------------------------------------------------------
// Gated DeltaNet recurrence. One block per head, 512 threads.
// Thread t: vrow = t/4, seg = t%4 owning state S[vrow, seg*32 .. seg*32+31]
// Full 128x128 state in registers (32 floats/thread).
// ---------------------------------------------------------------------------
__global__ __launch_bounds__(512) void recurrence(const float* __restrict__ q,
                                                  const float* __restrict__ k,
                                                  const float* __restrict__ v,
                                                  const float* __restrict__ alpha,
                                                  const float* __restrict__ beta,
                                                  float* __restrict__ o) {
    const int h = blockIdx.x;
    const int tid = threadIdx.x;
    const int vrow = tid >> 2;
    const int seg = tid & 3;
    const int base = seg * 32;

    __shared__ float ksh[2][DK], qsh[2][DK], vsh[2][DV], absh[2][2];

    float s[32];
#pragma unroll
    for (int j = 0; j < 32; j++) s[j] = 0.f;

    const int hoff = h * DK;
    // preload t=0 into buffer 0
    if (tid < 128)            ksh[0][tid]        = k[(size_t)0 * HID + hoff + tid];
    else if (tid < 256)       qsh[0][tid - 128]  = q[(size_t)0 * HID + hoff + (tid - 128)];
    else if (tid < 384)       vsh[0][tid - 256]  = v[(size_t)0 * HID + hoff + (tid - 256)];
    else if (tid == 384) { absh[0][0] = alpha[0 * NH + h]; absh[0][1] = beta[0 * NH + h]; }

    for (int t = 0; t < S_LEN; t++) {
        const int buf = t & 1;
        __syncthreads();
        // prefetch t+1 into buf^1
        if (t + 1 < S_LEN) {
            const size_t off = (size_t)(t + 1) * HID + hoff;
            if (tid < 128)        ksh[buf ^ 1][tid]       = k[off + tid];
            else if (tid < 256)   qsh[buf ^ 1][tid - 128] = q[off + (tid - 128)];
            else if (tid < 384)   vsh[buf ^ 1][tid - 256] = v[off + (tid - 256)];
            else if (tid == 384) {
                absh[buf ^ 1][0] = alpha[(t + 1) * NH + h];
                absh[buf ^ 1][1] = beta [(t + 1) * NH + h];
            }
        }
        const float a = absh[buf][0];
        const float b = absh[buf][1];

        // Sk = S . k_t  (partial over this thread's 32 cols)
        float d0 = 0.f, d1 = 0.f, d2 = 0.f, d3 = 0.f;
#pragma unroll
        for (int j = 0; j < 32; j += 4) {
            d0 = fmaf(s[j + 0], ksh[buf][base + j + 0], d0);
            d1 = fmaf(s[j + 1], ksh[buf][base + j + 1], d1);
            d2 = fmaf(s[j + 2], ksh[buf][base + j + 2], d2);
            d3 = fmaf(s[j + 3], ksh[buf][base + j + 3], d3);
        }
        float dot = (d0 + d1) + (d2 + d3);
        dot += __shfl_xor_sync(0xffffffffu, dot, 1);
        dot += __shfl_xor_sync(0xffffffffu, dot, 2);
        const float err = dot - vsh[buf][vrow];
        const float berr = b * err;

        // S = a*S - b*err*k ; o_partial = S_new . q_t
        float o0 = 0.f, o1 = 0.f, o2 = 0.f, o3 = 0.f;
#pragma unroll
        for (int j = 0; j < 32; j += 4) {
#pragma unroll
            for (int u = 0; u < 4; u++) {
                const float kv = ksh[buf][base + j + u];
                const float sn = fmaf(a, s[j + u], -berr * kv);
                s[j + u] = sn;
                const float qv = qsh[buf][base + j + u];
                if (u == 0) o0 = fmaf(sn, qv, o0);
                else if (u == 1) o1 = fmaf(sn, qv, o1);
                else if (u == 2) o2 = fmaf(sn, qv, o2);
                else o3 = fmaf(sn, qv, o3);
            }
        }
        float ov = (o0 + o1) + (o2 + o3);
        ov += __shfl_xor_sync(0xffffffffu, ov, 1);
        ov += __shfl_xor_sync(0xffffffffu, ov, 2);
        if (seg == 0) o[(size_t)t * HID + hoff + vrow] = ov;
    }
}

// ---------------------------------------------------------------------------
// LayerNorm over DV + sigmoid gate. One block of 128 per (t,h) row.
// ---------------------------------------------------------------------------
__global__ __launch_bounds__(128) void ln_gate(const float* __restrict__ o,
                                               const float* __restrict__ gb,
                                               const float* __restrict__ ln_g,
                                               const float* __restrict__ ln_b,
                                               float* __restrict__ out) {
    const int row = blockIdx.x;       // t*8 + h
    const int d = threadIdx.x;        // 0..127
    const size_t idx = (size_t)row * DV + d;   // == t*1024 + h*128 + d
    const float val = o[idx];

    __shared__ float red[4], red2[4];
    float sum = val;
#pragma unroll
    for (int off = 16; off > 0; off >>= 1) sum += __shfl_down_sync(0xffffffffu, sum, off);
    if ((d & 31) == 0) red[d >> 5] = sum;
    __syncthreads();
    const float mu = (red[0] + red[1] + red[2] + red[3]) * (1.f / DV);
    const float diff = val - mu;
    float sq = diff * diff;
#pragma unroll
    for (int off = 16; off > 0; off >>= 1) sq += __shfl_down_sync(0xffffffffu, sq, off);
    if ((d & 31) == 0) red2[d >> 5] = sq;
    __syncthreads();
    const float var = (red2[0] + red2[1] + red2[2] + red2[3]) * (1.f / DV);
    const float y = diff * rsqrtf(var + EPS) * ln_g[d] + ln_b[d];
    const float gate = 1.f / (1.f + expf(-gb[idx]));
    out[idx] = y * gate;
}

// ---------------------------------------------------------------------------
// Launch
// ---------------------------------------------------------------------------
extern "C" void kernel_launch(void* const* d_in, const int* in_sizes, int n_in,
                              void* d_out, int out_size) {
    const float* x       = (const float*)d_in[0];
    const float* Wq      = (const float*)d_in[1];
    const float* Wk      = (const float*)d_in[2];
    const float* Wv      = (const float*)d_in[3];
    const float* cqw     = (const float*)d_in[4];
    const float* cqb     = (const float*)d_in[5];
    const float* ckw     = (const float*)d_in[6];
    const float* ckb     = (const float*)d_in[7];
    const float* cvw     = (const float*)d_in[8];
    const float* cvb     = (const float*)d_in[9];
    const float* Wa      = (const float*)d_in[10];
    const float* ba      = (const float*)d_in[11];
    const float* Wb      = (const float*)d_in[12];
    const float* bb      = (const float*)d_in[13];
    const float* Wg      = (const float*)d_in[14];
    const float* ln_g    = (const float*)d_in[15];
    const float* ln_b    = (const float*)d_in[16];
    const float* Wo      = (const float*)d_in[17];
    float* out = (float*)d_out;

    float *qb, *kb, *vb, *qc, *kc, *vc, *gb, *ob, *o2, *al, *be;
    cudaGetSymbolAddress((void**)&qb, g_qb);
    cudaGetSymbolAddress((void**)&kb, g_kb);
    cudaGetSymbolAddress((void**)&vb, g_vb);
    cudaGetSymbolAddress((void**)&qc, g_qc);
    cudaGetSymbolAddress((void**)&kc, g_kc);
    cudaGetSymbolAddress((void**)&vc, g_vc);
    cudaGetSymbolAddress((void**)&gb, g_gb);
    cudaGetSymbolAddress((void**)&ob, g_ob);
    cudaGetSymbolAddress((void**)&o2, g_o2);
    cudaGetSymbolAddress((void**)&al, g_alpha);
    cudaGetSymbolAddress((void**)&be, g_beta);

    dim3 gg(HID / 128, S_LEN / 128);   // (8,16)
    sgemm_tn<<<gg, 256>>>(x, Wq, qb, S_LEN, HID, HID);
    sgemm_tn<<<gg, 256>>>(x, Wk, kb, S_LEN, HID, HID);
    sgemm_tn<<<gg, 256>>>(x, Wv, vb, S_LEN, HID, HID);
    sgemm_tn<<<gg, 256>>>(x, Wg, gb, S_LEN, HID, HID);

    ab_kernel<<<S_LEN, 256>>>(x, Wa, ba, Wb, bb, al, be);

    const int ew = S_LEN * HID / 256;
    conv_silu<<<ew, 256>>>(qb, cqw, cqb, qc, 1.0f);
    conv_silu<<<ew, 256>>>(kb, ckw, ckb, kc, SCALE);
    conv_silu<<<ew, 256>>>(vb, cvw, cvb, vc, 1.0f);

    recurrence<<<NH, 512>>>(qc, kc, vc, al, be, ob);

    ln_gate<<<S_LEN * NH, 128>>>(ob, gb, ln_g, ln_b, o2);

    sgemm_tn<<<gg, 256>>>(o2, Wo, out, S_LEN, HID, HID);
}

// round 3
// speedup vs baseline: 2.3001x; 2.3001x over previous
#include <cuda_runtime.h>
#include <cuda_bf16.h>
#include <math.h>

// Problem constants
#define S_LEN 2048
#define HID   1024
#define NH    8
#define DK    128
#define DV    128
#define KCONV 4
#define SCALE 0.08838834764831845f   // 128^-0.5
#define EPS   1e-5f

// ---------------------------------------------------------------------------
// Static device scratch (no allocation allowed)
// ---------------------------------------------------------------------------
__device__ float g_qb[S_LEN * HID];   // x@Wq^T (pre-conv)
__device__ float g_kb[S_LEN * HID];
__device__ float g_vb[S_LEN * HID];
__device__ float g_qc[S_LEN * HID];   // post conv+silu
__device__ float g_kc[S_LEN * HID];
__device__ float g_vc[S_LEN * HID];
__device__ float g_gb[S_LEN * HID];   // x@Wg^T (pre-sigmoid)
__device__ float g_ob[S_LEN * HID];   // recurrence output o[t,h,v]
__device__ float g_o2[S_LEN * HID];   // post LN*gate
__device__ float g_alpha[S_LEN * NH];
__device__ float g_beta [S_LEN * NH];

// ---------------------------------------------------------------------------
// SGEMM: C[M,N] = A[M,K] * B[N,K]^T   (A row-major, B row-major [N,K])
// 128x128 block tile, 8x8 microtile, K-chunk 8, double-buffered smem.
// ---------------------------------------------------------------------------
__global__ __launch_bounds__(256) void sgemm_tn(const float* __restrict__ A,
                                                const float* __restrict__ B,
                                                float* __restrict__ C,
                                                int M, int N, int K) {
    __shared__ float As[2][8][128];
    __shared__ float Bs[2][8][128];

    const int tid = threadIdx.x;
    const int bm = blockIdx.y * 128;
    const int bn = blockIdx.x * 128;

    const int lr = tid >> 1;          // 0..127 row within tile
    const int lc = (tid & 1) * 4;     // 0 or 4 col within 8-chunk

    const int tx = tid & 15;          // 0..15  -> N subtile
    const int ty = tid >> 4;          // 0..15  -> M subtile

    float acc[8][8];
#pragma unroll
    for (int i = 0; i < 8; i++)
#pragma unroll
        for (int j = 0; j < 8; j++) acc[i][j] = 0.f;

    float4 av = *reinterpret_cast<const float4*>(&A[(size_t)(bm + lr) * K + lc]);
    float4 bv = *reinterpret_cast<const float4*>(&B[(size_t)(bn + lr) * K + lc]);
    As[0][lc + 0][lr] = av.x; As[0][lc + 1][lr] = av.y;
    As[0][lc + 2][lr] = av.z; As[0][lc + 3][lr] = av.w;
    Bs[0][lc + 0][lr] = bv.x; Bs[0][lc + 1][lr] = bv.y;
    Bs[0][lc + 2][lr] = bv.z; Bs[0][lc + 3][lr] = bv.w;
    __syncthreads();

    for (int kt = 0; kt < K; kt += 8) {
        const int cur = (kt >> 3) & 1;
        const int nxt = cur ^ 1;
        float4 an, bn4;
        const bool has_next = (kt + 8) < K;
        if (has_next) {
            an  = *reinterpret_cast<const float4*>(&A[(size_t)(bm + lr) * K + kt + 8 + lc]);
            bn4 = *reinterpret_cast<const float4*>(&B[(size_t)(bn + lr) * K + kt + 8 + lc]);
        }
#pragma unroll
        for (int kk = 0; kk < 8; kk++) {
            float4 a0 = *reinterpret_cast<const float4*>(&As[cur][kk][ty * 8]);
            float4 a1 = *reinterpret_cast<const float4*>(&As[cur][kk][ty * 8 + 4]);
            float4 b0 = *reinterpret_cast<const float4*>(&Bs[cur][kk][tx * 8]);
            float4 b1 = *reinterpret_cast<const float4*>(&Bs[cur][kk][tx * 8 + 4]);
            float ar[8] = {a0.x, a0.y, a0.z, a0.w, a1.x, a1.y, a1.z, a1.w};
            float br[8] = {b0.x, b0.y, b0.z, b0.w, b1.x, b1.y, b1.z, b1.w};
#pragma unroll
            for (int i = 0; i < 8; i++)
#pragma unroll
                for (int j = 0; j < 8; j++) acc[i][j] = fmaf(ar[i], br[j], acc[i][j]);
        }
        if (has_next) {
            As[nxt][lc + 0][lr] = an.x;  As[nxt][lc + 1][lr] = an.y;
            As[nxt][lc + 2][lr] = an.z;  As[nxt][lc + 3][lr] = an.w;
            Bs[nxt][lc + 0][lr] = bn4.x; Bs[nxt][lc + 1][lr] = bn4.y;
            Bs[nxt][lc + 2][lr] = bn4.z; Bs[nxt][lc + 3][lr] = bn4.w;
            __syncthreads();
        }
    }

#pragma unroll
    for (int i = 0; i < 8; i++) {
        const size_t row = (size_t)(bm + ty * 8 + i) * N + bn + tx * 8;
        float4 c0 = make_float4(acc[i][0], acc[i][1], acc[i][2], acc[i][3]);
        float4 c1 = make_float4(acc[i][4], acc[i][5], acc[i][6], acc[i][7]);
        *reinterpret_cast<float4*>(&C[row])     = c0;
        *reinterpret_cast<float4*>(&C[row + 4]) = c1;
    }
}

// ---------------------------------------------------------------------------
// alpha/beta projections
// ---------------------------------------------------------------------------
__global__ __launch_bounds__(256) void ab_kernel(const float* __restrict__ x,
                                                 const float* __restrict__ Wa,
                                                 const float* __restrict__ ba,
                                                 const float* __restrict__ Wb,
                                                 const float* __restrict__ bb,
                                                 float* __restrict__ alpha,
                                                 float* __restrict__ beta) {
    const int t = blockIdx.x;
    const int w = threadIdx.x >> 5;   // head
    const int lane = threadIdx.x & 31;
    const float* xr = x + (size_t)t * HID;
    const float* war = Wa + (size_t)w * HID;
    const float* wbr = Wb + (size_t)w * HID;
    float sa = 0.f, sb = 0.f;
    for (int i = lane; i < HID; i += 32) {
        float xv = xr[i];
        sa = fmaf(xv, war[i], sa);
        sb = fmaf(xv, wbr[i], sb);
    }
#pragma unroll
    for (int off = 16; off > 0; off >>= 1) {
        sa += __shfl_down_sync(0xffffffffu, sa, off);
        sb += __shfl_down_sync(0xffffffffu, sb, off);
    }
    if (lane == 0) {
        alpha[t * NH + w] = 1.f / (1.f + expf(-(sa + ba[w])));
        beta [t * NH + w] = 1.f / (1.f + expf(-(sb + bb[w])));
    }
}

// ---------------------------------------------------------------------------
// Depthwise causal conv (K=4) + bias + SiLU (+ optional scale for K path)
// ---------------------------------------------------------------------------
__global__ __launch_bounds__(256) void conv_silu(const float* __restrict__ in,
                                                 const float* __restrict__ w,
                                                 const float* __restrict__ b,
                                                 float* __restrict__ out,
                                                 float scale) {
    const int idx = blockIdx.x * 256 + threadIdx.x;  // over S*HID
    const int t = idx >> 10;
    const int c = idx & 1023;
    float acc = b[c];
#pragma unroll
    for (int j = 0; j < KCONV; j++) {
        const int tt = t + j - (KCONV - 1);
        if (tt >= 0) acc = fmaf(in[((size_t)tt << 10) + c], w[c * KCONV + j], acc);
    }
    const float sil = acc / (1.f + expf(-acc));
    out[idx] = sil * scale;
}

// ---------------------------------------------------------------------------
// Gated DeltaNet recurrence v2 — row-parallel, barrier-free.
// State rows are independent: S_t[r,:] = a*S[r,:] + (b*(v_t[r]-S[r,:].k_t))*k_t
// Mapping: 8 lanes per row (16 state floats per lane), 4 rows per warp,
// 8 warps per block (32 rows), grid = 8 heads * 4 row-groups = 32 blocks.
// All communication = shfl_xor within 8-lane groups. No smem, no barriers.
// ---------------------------------------------------------------------------
__global__ __launch_bounds__(256) void recurrence2(const float* __restrict__ q,
                                                   const float* __restrict__ k,
                                                   const float* __restrict__ v,
                                                   const float* __restrict__ alpha,
                                                   const float* __restrict__ beta,
                                                   float* __restrict__ o) {
    const int h  = blockIdx.x >> 2;            // head 0..7
    const int rg = blockIdx.x & 3;             // row group
    const int wid  = threadIdx.x >> 5;
    const int lane = threadIdx.x & 31;
    const int row = rg * 32 + wid * 4 + (lane >> 3);   // v-row 0..127
    const int seg = lane & 7;                  // 16-col k segment
    const int hoff = h * DK;

    const float* kp = k + hoff + seg * 16;     // + t*HID
    const float* qp = q + hoff + seg * 16;
    const float* vp = v + hoff + row;
    const float* ap = alpha + h;
    const float* bp = beta + h;
    float* op = o + hoff + row;

    float s[16];
#pragma unroll
    for (int j = 0; j < 16; j++) s[j] = 0.f;

    for (int t = 0; t < S_LEN; t++) {
        const size_t off = (size_t)t * HID;

        // L1 prefetch two steps ahead (covers DRAM/L2 latency)
        if (t + 2 < S_LEN) {
            const char* pk = (const char*)(kp + off + 2 * HID);
            const char* pq = (const char*)(qp + off + 2 * HID);
            const char* pv = (const char*)(vp + off + 2 * HID);
            asm volatile("prefetch.global.L1 [%0];" :: "l"(pk));
            asm volatile("prefetch.global.L1 [%0];" :: "l"(pq));
            asm volatile("prefetch.global.L1 [%0];" :: "l"(pv));
        }

        // scalar loads first so their latency overlaps the vector loads
        const float a  = __ldg(ap + (size_t)t * NH);
        const float b  = __ldg(bp + (size_t)t * NH);
        const float vt = __ldg(vp + off);

        float kk[16], qq[16];
#pragma unroll
        for (int i = 0; i < 4; i++) {
            float4 kv4 = __ldg(reinterpret_cast<const float4*>(kp + off) + i);
            float4 qv4 = __ldg(reinterpret_cast<const float4*>(qp + off) + i);
            kk[4*i+0] = kv4.x; kk[4*i+1] = kv4.y; kk[4*i+2] = kv4.z; kk[4*i+3] = kv4.w;
            qq[4*i+0] = qv4.x; qq[4*i+1] = qv4.y; qq[4*i+2] = qv4.z; qq[4*i+3] = qv4.w;
        }

        // dot = S[row,:] . k_t  (partial over 16, reduce over 8 lanes)
        float d0 = 0.f, d1 = 0.f, d2 = 0.f, d3 = 0.f;
#pragma unroll
        for (int j = 0; j < 16; j += 4) {
            d0 = fmaf(s[j + 0], kk[j + 0], d0);
            d1 = fmaf(s[j + 1], kk[j + 1], d1);
            d2 = fmaf(s[j + 2], kk[j + 2], d2);
            d3 = fmaf(s[j + 3], kk[j + 3], d3);
        }
        float dot = (d0 + d1) + (d2 + d3);
        dot += __shfl_xor_sync(0xffffffffu, dot, 1);
        dot += __shfl_xor_sync(0xffffffffu, dot, 2);
        dot += __shfl_xor_sync(0xffffffffu, dot, 4);

        const float nb = b * (vt - dot);      // -b*err

        // S = a*S + nb*k ; o_partial = S_new . q
        float o0 = 0.f, o1 = 0.f, o2 = 0.f, o3 = 0.f;
#pragma unroll
        for (int j = 0; j < 16; j += 4) {
            float sn0 = fmaf(a, s[j + 0], nb * kk[j + 0]);
            float sn1 = fmaf(a, s[j + 1], nb * kk[j + 1]);
            float sn2 = fmaf(a, s[j + 2], nb * kk[j + 2]);
            float sn3 = fmaf(a, s[j + 3], nb * kk[j + 3]);
            s[j + 0] = sn0; s[j + 1] = sn1; s[j + 2] = sn2; s[j + 3] = sn3;
            o0 = fmaf(sn0, qq[j + 0], o0);
            o1 = fmaf(sn1, qq[j + 1], o1);
            o2 = fmaf(sn2, qq[j + 2], o2);
            o3 = fmaf(sn3, qq[j + 3], o3);
        }
        float ov = (o0 + o1) + (o2 + o3);
        ov += __shfl_xor_sync(0xffffffffu, ov, 1);
        ov += __shfl_xor_sync(0xffffffffu, ov, 2);
        ov += __shfl_xor_sync(0xffffffffu, ov, 4);
        if (seg == 0) op[off] = ov;
    }
}

// ---------------------------------------------------------------------------
// LayerNorm over DV + sigmoid gate. One block of 128 per (t,h) row.
// ---------------------------------------------------------------------------
__global__ __launch_bounds__(128) void ln_gate(const float* __restrict__ o,
                                               const float* __restrict__ gb,
                                               const float* __restrict__ ln_g,
                                               const float* __restrict__ ln_b,
                                               float* __restrict__ out) {
    const int row = blockIdx.x;       // t*8 + h
    const int d = threadIdx.x;        // 0..127
    const size_t idx = (size_t)row * DV + d;
    const float val = o[idx];

    __shared__ float red[4], red2[4];
    float sum = val;
#pragma unroll
    for (int off = 16; off > 0; off >>= 1) sum += __shfl_down_sync(0xffffffffu, sum, off);
    if ((d & 31) == 0) red[d >> 5] = sum;
    __syncthreads();
    const float mu = (red[0] + red[1] + red[2] + red[3]) * (1.f / DV);
    const float diff = val - mu;
    float sq = diff * diff;
#pragma unroll
    for (int off = 16; off > 0; off >>= 1) sq += __shfl_down_sync(0xffffffffu, sq, off);
    if ((d & 31) == 0) red2[d >> 5] = sq;
    __syncthreads();
    const float var = (red2[0] + red2[1] + red2[2] + red2[3]) * (1.f / DV);
    const float y = diff * rsqrtf(var + EPS) * ln_g[d] + ln_b[d];
    const float gate = 1.f / (1.f + expf(-gb[idx]));
    out[idx] = y * gate;
}

// ---------------------------------------------------------------------------
// Launch
// ---------------------------------------------------------------------------
extern "C" void kernel_launch(void* const* d_in, const int* in_sizes, int n_in,
                              void* d_out, int out_size) {
    const float* x       = (const float*)d_in[0];
    const float* Wq      = (const float*)d_in[1];
    const float* Wk      = (const float*)d_in[2];
    const float* Wv      = (const float*)d_in[3];
    const float* cqw     = (const float*)d_in[4];
    const float* cqb     = (const float*)d_in[5];
    const float* ckw     = (const float*)d_in[6];
    const float* ckb     = (const float*)d_in[7];
    const float* cvw     = (const float*)d_in[8];
    const float* cvb     = (const float*)d_in[9];
    const float* Wa      = (const float*)d_in[10];
    const float* ba      = (const float*)d_in[11];
    const float* Wb      = (const float*)d_in[12];
    const float* bb      = (const float*)d_in[13];
    const float* Wg      = (const float*)d_in[14];
    const float* ln_g    = (const float*)d_in[15];
    const float* ln_b    = (const float*)d_in[16];
    const float* Wo      = (const float*)d_in[17];
    float* out = (float*)d_out;

    float *qb, *kb, *vb, *qc, *kc, *vc, *gb, *ob, *o2, *al, *be;
    cudaGetSymbolAddress((void**)&qb, g_qb);
    cudaGetSymbolAddress((void**)&kb, g_kb);
    cudaGetSymbolAddress((void**)&vb, g_vb);
    cudaGetSymbolAddress((void**)&qc, g_qc);
    cudaGetSymbolAddress((void**)&kc, g_kc);
    cudaGetSymbolAddress((void**)&vc, g_vc);
    cudaGetSymbolAddress((void**)&gb, g_gb);
    cudaGetSymbolAddress((void**)&ob, g_ob);
    cudaGetSymbolAddress((void**)&o2, g_o2);
    cudaGetSymbolAddress((void**)&al, g_alpha);
    cudaGetSymbolAddress((void**)&be, g_beta);

    dim3 gg(HID / 128, S_LEN / 128);   // (8,16)
    sgemm_tn<<<gg, 256>>>(x, Wq, qb, S_LEN, HID, HID);
    sgemm_tn<<<gg, 256>>>(x, Wk, kb, S_LEN, HID, HID);
    sgemm_tn<<<gg, 256>>>(x, Wv, vb, S_LEN, HID, HID);
    sgemm_tn<<<gg, 256>>>(x, Wg, gb, S_LEN, HID, HID);

    ab_kernel<<<S_LEN, 256>>>(x, Wa, ba, Wb, bb, al, be);

    const int ew = S_LEN * HID / 256;
    conv_silu<<<ew, 256>>>(qb, cqw, cqb, qc, 1.0f);
    conv_silu<<<ew, 256>>>(kb, ckw, ckb, kc, SCALE);
    conv_silu<<<ew, 256>>>(vb, cvw, cvb, vc, 1.0f);

    recurrence2<<<32, 256>>>(qc, kc, vc, al, be, ob);

    ln_gate<<<S_LEN * NH, 128>>>(ob, gb, ln_g, ln_b, o2);

    sgemm_tn<<<gg, 256>>>(o2, Wo, out, S_LEN, HID, HID);
}

// round 5
// speedup vs baseline: 3.4329x; 1.4925x over previous
#include <cuda_runtime.h>
#include <cuda_bf16.h>
#include <math.h>

#define S_LEN 2048
#define HID   1024
#define NH    8
#define DK    128
#define DV    128
#define KCONV 4
#define SCALE 0.08838834764831845f   // 128^-0.5
#define EPS   1e-5f

// ---------------------------------------------------------------------------
// Static device scratch
// ---------------------------------------------------------------------------
__device__ float g_qb[S_LEN * HID];
__device__ float g_kb[S_LEN * HID];
__device__ float g_vb[S_LEN * HID];
__device__ float g_qc[S_LEN * HID];
__device__ float g_kc[S_LEN * HID];
__device__ float g_vc[S_LEN * HID];
__device__ float g_gb[S_LEN * HID];
__device__ float g_ob[S_LEN * HID];
__device__ float g_o2[S_LEN * HID];
__device__ float g_alpha[S_LEN * NH];
__device__ float g_beta [S_LEN * NH];

// ---------------------------------------------------------------------------
// SGEMM: C[M,N] = A[M,K] * B[N,K]^T. 128x128 tile, 8x8 microtile, double-buffer.
// blockIdx.z selects one of up to 4 (B, C) pairs -> one launch for Q/K/V/G.
// __launch_bounds__(256,2): 2 blocks/SM to raise issue occupancy.
// ---------------------------------------------------------------------------
__global__ __launch_bounds__(256, 2) void sgemm_tn4(const float* __restrict__ A,
                                                    const float* __restrict__ B0,
                                                    const float* __restrict__ B1,
                                                    const float* __restrict__ B2,
                                                    const float* __restrict__ B3,
                                                    float* __restrict__ C0,
                                                    float* __restrict__ C1,
                                                    float* __restrict__ C2,
                                                    float* __restrict__ C3,
                                                    int M, int N, int K) {
    const int z = blockIdx.z;
    const float* B = (z == 0) ? B0 : (z == 1) ? B1 : (z == 2) ? B2 : B3;
    float*       C = (z == 0) ? C0 : (z == 1) ? C1 : (z == 2) ? C2 : C3;

    __shared__ float As[2][8][128];
    __shared__ float Bs[2][8][128];

    const int tid = threadIdx.x;
    const int bm = blockIdx.y * 128;
    const int bn = blockIdx.x * 128;

    const int lr = tid >> 1;
    const int lc = (tid & 1) * 4;
    const int tx = tid & 15;
    const int ty = tid >> 4;

    float acc[8][8];
#pragma unroll
    for (int i = 0; i < 8; i++)
#pragma unroll
        for (int j = 0; j < 8; j++) acc[i][j] = 0.f;

    float4 av = *reinterpret_cast<const float4*>(&A[(size_t)(bm + lr) * K + lc]);
    float4 bv = *reinterpret_cast<const float4*>(&B[(size_t)(bn + lr) * K + lc]);
    As[0][lc + 0][lr] = av.x; As[0][lc + 1][lr] = av.y;
    As[0][lc + 2][lr] = av.z; As[0][lc + 3][lr] = av.w;
    Bs[0][lc + 0][lr] = bv.x; Bs[0][lc + 1][lr] = bv.y;
    Bs[0][lc + 2][lr] = bv.z; Bs[0][lc + 3][lr] = bv.w;
    __syncthreads();

    for (int kt = 0; kt < K; kt += 8) {
        const int cur = (kt >> 3) & 1;
        const int nxt = cur ^ 1;
        float4 an, bn4;
        const bool has_next = (kt + 8) < K;
        if (has_next) {
            an  = *reinterpret_cast<const float4*>(&A[(size_t)(bm + lr) * K + kt + 8 + lc]);
            bn4 = *reinterpret_cast<const float4*>(&B[(size_t)(bn + lr) * K + kt + 8 + lc]);
        }
#pragma unroll
        for (int kk = 0; kk < 8; kk++) {
            float4 a0 = *reinterpret_cast<const float4*>(&As[cur][kk][ty * 8]);
            float4 a1 = *reinterpret_cast<const float4*>(&As[cur][kk][ty * 8 + 4]);
            float4 b0 = *reinterpret_cast<const float4*>(&Bs[cur][kk][tx * 8]);
            float4 b1 = *reinterpret_cast<const float4*>(&Bs[cur][kk][tx * 8 + 4]);
            float ar[8] = {a0.x, a0.y, a0.z, a0.w, a1.x, a1.y, a1.z, a1.w};
            float br[8] = {b0.x, b0.y, b0.z, b0.w, b1.x, b1.y, b1.z, b1.w};
#pragma unroll
            for (int i = 0; i < 8; i++)
#pragma unroll
                for (int j = 0; j < 8; j++) acc[i][j] = fmaf(ar[i], br[j], acc[i][j]);
        }
        if (has_next) {
            As[nxt][lc + 0][lr] = an.x;  As[nxt][lc + 1][lr] = an.y;
            As[nxt][lc + 2][lr] = an.z;  As[nxt][lc + 3][lr] = an.w;
            Bs[nxt][lc + 0][lr] = bn4.x; Bs[nxt][lc + 1][lr] = bn4.y;
            Bs[nxt][lc + 2][lr] = bn4.z; Bs[nxt][lc + 3][lr] = bn4.w;
            __syncthreads();
        }
    }

#pragma unroll
    for (int i = 0; i < 8; i++) {
        const size_t row = (size_t)(bm + ty * 8 + i) * N + bn + tx * 8;
        *reinterpret_cast<float4*>(&C[row])     = make_float4(acc[i][0], acc[i][1], acc[i][2], acc[i][3]);
        *reinterpret_cast<float4*>(&C[row + 4]) = make_float4(acc[i][4], acc[i][5], acc[i][6], acc[i][7]);
    }
}

// ---------------------------------------------------------------------------
// alpha/beta projections
// ---------------------------------------------------------------------------
__global__ __launch_bounds__(256) void ab_kernel(const float* __restrict__ x,
                                                 const float* __restrict__ Wa,
                                                 const float* __restrict__ ba,
                                                 const float* __restrict__ Wb,
                                                 const float* __restrict__ bb,
                                                 float* __restrict__ alpha,
                                                 float* __restrict__ beta) {
    const int t = blockIdx.x;
    const int w = threadIdx.x >> 5;
    const int lane = threadIdx.x & 31;
    const float* xr = x + (size_t)t * HID;
    const float* war = Wa + (size_t)w * HID;
    const float* wbr = Wb + (size_t)w * HID;
    float sa = 0.f, sb = 0.f;
    for (int i = lane; i < HID; i += 32) {
        float xv = xr[i];
        sa = fmaf(xv, war[i], sa);
        sb = fmaf(xv, wbr[i], sb);
    }
#pragma unroll
    for (int off = 16; off > 0; off >>= 1) {
        sa += __shfl_down_sync(0xffffffffu, sa, off);
        sb += __shfl_down_sync(0xffffffffu, sb, off);
    }
    if (lane == 0) {
        alpha[t * NH + w] = 1.f / (1.f + expf(-(sa + ba[w])));
        beta [t * NH + w] = 1.f / (1.f + expf(-(sb + bb[w])));
    }
}

// ---------------------------------------------------------------------------
// Fused depthwise causal conv (K=4) + bias + SiLU for q/k/v. blockIdx.y picks.
// ---------------------------------------------------------------------------
__global__ __launch_bounds__(256) void conv_silu3(const float* __restrict__ inq,
                                                  const float* __restrict__ ink,
                                                  const float* __restrict__ inv,
                                                  const float* __restrict__ wq,
                                                  const float* __restrict__ bq,
                                                  const float* __restrict__ wk,
                                                  const float* __restrict__ bk,
                                                  const float* __restrict__ wv,
                                                  const float* __restrict__ bv,
                                                  float* __restrict__ outq,
                                                  float* __restrict__ outk,
                                                  float* __restrict__ outv) {
    const int z = blockIdx.y;
    const float* in  = (z == 0) ? inq : (z == 1) ? ink : inv;
    const float* w   = (z == 0) ? wq  : (z == 1) ? wk  : wv;
    const float* b   = (z == 0) ? bq  : (z == 1) ? bk  : bv;
    float*       out = (z == 0) ? outq: (z == 1) ? outk: outv;
    const float scale = (z == 1) ? SCALE : 1.0f;

    const int idx = blockIdx.x * 256 + threadIdx.x;
    const int t = idx >> 10;
    const int c = idx & 1023;
    float acc = b[c];
#pragma unroll
    for (int j = 0; j < KCONV; j++) {
        const int tt = t + j - (KCONV - 1);
        if (tt >= 0) acc = fmaf(in[((size_t)tt << 10) + c], w[c * KCONV + j], acc);
    }
    const float sil = acc / (1.f + expf(-acc));
    out[idx] = sil * scale;
}

// ---------------------------------------------------------------------------
// Gated DeltaNet recurrence v3 — lookahead-linearized, register-pipelined.
//
// Row-parallel (rows independent). 8 lanes/row, 16 state floats per lane.
// 64 blocks x 128 threads: 1 warp/SMSP. 8 heads x 8 row-groups of 16 rows.
//
// Lookahead: dot_{t+1} = s_t.k_{t+1} = a_t*P + nb_t*R with
//   P = s_{t-1}.k_{t+1}, R = k_t.k_{t+1} (both reducible before nb_t known)
// => scalar recurrence chain is just fma+sub+mul (~16cyc); shuffles pipeline.
// ---------------------------------------------------------------------------
__global__ __launch_bounds__(128) void recurrence3(const float* __restrict__ q,
                                                   const float* __restrict__ k,
                                                   const float* __restrict__ v,
                                                   const float* __restrict__ alpha,
                                                   const float* __restrict__ beta,
                                                   float* __restrict__ o) {
    const int h  = blockIdx.x >> 3;            // head 0..7
    const int rg = blockIdx.x & 7;             // row group (16 rows)
    const int wid  = threadIdx.x >> 5;         // 0..3
    const int lane = threadIdx.x & 31;
    const int row = rg * 16 + wid * 4 + (lane >> 3);
    const int seg = lane & 7;
    const int hoff = h * DK;

    const float* kp = k + hoff + seg * 16;
    const float* qp = q + hoff + seg * 16;
    const float* vp = v + hoff + row;
    const float* ap = alpha + h;
    const float* bp = beta + h;
    float* op = o + hoff + row;

    float s[16];
#pragma unroll
    for (int j = 0; j < 16; j++) s[j] = 0.f;

    float kA[16], qA[16], kB[16], qB[16];
    float vA, aA, bA, vB, aB, bB;

#define LOADSTEP(K_, Q_, V_, A_, B_, T_) {                                        \
    const size_t off_ = (size_t)(T_) * HID;                                       \
    _Pragma("unroll")                                                             \
    for (int i_ = 0; i_ < 4; i_++) {                                              \
        float4 kv_ = __ldg(reinterpret_cast<const float4*>(kp + off_) + i_);      \
        float4 qv_ = __ldg(reinterpret_cast<const float4*>(qp + off_) + i_);      \
        K_[4*i_+0] = kv_.x; K_[4*i_+1] = kv_.y; K_[4*i_+2] = kv_.z; K_[4*i_+3] = kv_.w; \
        Q_[4*i_+0] = qv_.x; Q_[4*i_+1] = qv_.y; Q_[4*i_+2] = qv_.z; Q_[4*i_+3] = qv_.w; \
    }                                                                             \
    V_ = __ldg(vp + off_);                                                        \
    A_ = __ldg(ap + (size_t)(T_) * NH);                                           \
    B_ = __ldg(bp + (size_t)(T_) * NH);                                           \
}

#define RED8(x_) {                                                                \
    x_ += __shfl_xor_sync(0xffffffffu, x_, 1);                                    \
    x_ += __shfl_xor_sync(0xffffffffu, x_, 2);                                    \
    x_ += __shfl_xor_sync(0xffffffffu, x_, 4);                                    \
}

// One recurrence step. KC/QC/... = step-t inputs, KN = step-(t+1) k.
// After the body, KC/QC/VC/AC/BC are reloaded with step t+2 (clamped).
#define STEP(KC, QC, VC, AC, BC, KN, T_) {                                        \
    const float nb = BC * (VC - dot);        /* scalar chain */                   \
    float P0=0.f,P1=0.f,P2=0.f,P3=0.f, R0=0.f,R1=0.f,R2=0.f,R3=0.f;               \
    _Pragma("unroll")                                                             \
    for (int j = 0; j < 16; j += 4) {                                             \
        P0 = fmaf(s[j+0], KN[j+0], P0);  R0 = fmaf(KC[j+0], KN[j+0], R0);         \
        P1 = fmaf(s[j+1], KN[j+1], P1);  R1 = fmaf(KC[j+1], KN[j+1], R1);         \
        P2 = fmaf(s[j+2], KN[j+2], P2);  R2 = fmaf(KC[j+2], KN[j+2], R2);         \
        P3 = fmaf(s[j+3], KN[j+3], P3);  R3 = fmaf(KC[j+3], KN[j+3], R3);         \
    }                                                                             \
    float P = (P0 + P1) + (P2 + P3);                                              \
    float R = (R0 + R1) + (R2 + R3);                                              \
    float o0=0.f,o1=0.f,o2=0.f,o3=0.f;                                            \
    _Pragma("unroll")                                                             \
    for (int j = 0; j < 16; j += 4) {                                             \
        float sn0 = fmaf(AC, s[j+0], nb * KC[j+0]);                               \
        float sn1 = fmaf(AC, s[j+1], nb * KC[j+1]);                               \
        float sn2 = fmaf(AC, s[j+2], nb * KC[j+2]);                               \
        float sn3 = fmaf(AC, s[j+3], nb * KC[j+3]);                               \
        s[j+0]=sn0; s[j+1]=sn1; s[j+2]=sn2; s[j+3]=sn3;                           \
        o0 = fmaf(sn0, QC[j+0], o0);  o1 = fmaf(sn1, QC[j+1], o1);                \
        o2 = fmaf(sn2, QC[j+2], o2);  o3 = fmaf(sn3, QC[j+3], o3);                \
    }                                                                             \
    float ov = (o0 + o1) + (o2 + o3);                                             \
    RED8(P); RED8(R); RED8(ov);                                                   \
    dot = fmaf(AC, P, nb * R);                                                    \
    if (seg == 0) op[(size_t)(T_) * HID] = ov;                                    \
    /* prefetch far ahead, reload this buffer with t+2 */                         \
    {                                                                             \
        const int tpf = ((T_) + 6 < S_LEN) ? (T_) + 6 : (S_LEN - 1);              \
        asm volatile("prefetch.global.L1 [%0];" :: "l"((const char*)(kp + (size_t)tpf * HID))); \
        asm volatile("prefetch.global.L1 [%0];" :: "l"((const char*)(qp + (size_t)tpf * HID))); \
        const int tn = ((T_) + 2 < S_LEN) ? (T_) + 2 : (S_LEN - 1);               \
        LOADSTEP(KC, QC, VC, AC, BC, tn);                                         \
    }                                                                             \
}

    LOADSTEP(kA, qA, vA, aA, bA, 0);
    LOADSTEP(kB, qB, vB, aB, bB, 1);
    float dot = 0.f;   // s_{-1}.k_0 = 0

    for (int t = 0; t < S_LEN; t += 2) {
        STEP(kA, qA, vA, aA, bA, kB, t);
        STEP(kB, qB, vB, aB, bB, kA, t + 1);
    }
#undef STEP
#undef RED8
#undef LOADSTEP
}

// ---------------------------------------------------------------------------
// LayerNorm over DV + sigmoid gate.
// ---------------------------------------------------------------------------
__global__ __launch_bounds__(128) void ln_gate(const float* __restrict__ o,
                                               const float* __restrict__ gb,
                                               const float* __restrict__ ln_g,
                                               const float* __restrict__ ln_b,
                                               float* __restrict__ out) {
    const int row = blockIdx.x;
    const int d = threadIdx.x;
    const size_t idx = (size_t)row * DV + d;
    const float val = o[idx];

    __shared__ float red[4], red2[4];
    float sum = val;
#pragma unroll
    for (int off = 16; off > 0; off >>= 1) sum += __shfl_down_sync(0xffffffffu, sum, off);
    if ((d & 31) == 0) red[d >> 5] = sum;
    __syncthreads();
    const float mu = (red[0] + red[1] + red[2] + red[3]) * (1.f / DV);
    const float diff = val - mu;
    float sq = diff * diff;
#pragma unroll
    for (int off = 16; off > 0; off >>= 1) sq += __shfl_down_sync(0xffffffffu, sq, off);
    if ((d & 31) == 0) red2[d >> 5] = sq;
    __syncthreads();
    const float var = (red2[0] + red2[1] + red2[2] + red2[3]) * (1.f / DV);
    const float y = diff * rsqrtf(var + EPS) * ln_g[d] + ln_b[d];
    const float gate = 1.f / (1.f + expf(-gb[idx]));
    out[idx] = y * gate;
}

// ---------------------------------------------------------------------------
// Launch
// ---------------------------------------------------------------------------
extern "C" void kernel_launch(void* const* d_in, const int* in_sizes, int n_in,
                              void* d_out, int out_size) {
    const float* x       = (const float*)d_in[0];
    const float* Wq      = (const float*)d_in[1];
    const float* Wk      = (const float*)d_in[2];
    const float* Wv      = (const float*)d_in[3];
    const float* cqw     = (const float*)d_in[4];
    const float* cqb     = (const float*)d_in[5];
    const float* ckw     = (const float*)d_in[6];
    const float* ckb     = (const float*)d_in[7];
    const float* cvw     = (const float*)d_in[8];
    const float* cvb     = (const float*)d_in[9];
    const float* Wa      = (const float*)d_in[10];
    const float* ba      = (const float*)d_in[11];
    const float* Wb      = (const float*)d_in[12];
    const float* bb      = (const float*)d_in[13];
    const float* Wg      = (const float*)d_in[14];
    const float* ln_g    = (const float*)d_in[15];
    const float* ln_b    = (const float*)d_in[16];
    const float* Wo      = (const float*)d_in[17];
    float* out = (float*)d_out;

    float *qb, *kb, *vb, *qc, *kc, *vc, *gb, *ob, *o2, *al, *be;
    cudaGetSymbolAddress((void**)&qb, g_qb);
    cudaGetSymbolAddress((void**)&kb, g_kb);
    cudaGetSymbolAddress((void**)&vb, g_vb);
    cudaGetSymbolAddress((void**)&qc, g_qc);
    cudaGetSymbolAddress((void**)&kc, g_kc);
    cudaGetSymbolAddress((void**)&vc, g_vc);
    cudaGetSymbolAddress((void**)&gb, g_gb);
    cudaGetSymbolAddress((void**)&ob, g_ob);
    cudaGetSymbolAddress((void**)&o2, g_o2);
    cudaGetSymbolAddress((void**)&al, g_alpha);
    cudaGetSymbolAddress((void**)&be, g_beta);

    // Fused Q/K/V/G projections: one launch, 512 blocks
    dim3 g4(HID / 128, S_LEN / 128, 4);
    sgemm_tn4<<<g4, 256>>>(x, Wq, Wk, Wv, Wg, qb, kb, vb, gb, S_LEN, HID, HID);

    ab_kernel<<<S_LEN, 256>>>(x, Wa, ba, Wb, bb, al, be);

    dim3 gc(S_LEN * HID / 256, 3);
    conv_silu3<<<gc, 256>>>(qb, kb, vb, cqw, cqb, ckw, ckb, cvw, cvb, qc, kc, vc);

    recurrence3<<<64, 128>>>(qc, kc, vc, al, be, ob);

    ln_gate<<<S_LEN * NH, 128>>>(ob, gb, ln_g, ln_b, o2);

    dim3 g1(HID / 128, S_LEN / 128, 1);
    sgemm_tn4<<<g1, 256>>>(o2, Wo, Wo, Wo, Wo, out, out, out, out, S_LEN, HID, HID);
}

// round 6
// speedup vs baseline: 3.7873x; 1.1032x over previous
#include <cuda_runtime.h>
#include <cuda_bf16.h>
#include <math.h>

#define S_LEN 2048
#define HID   1024
#define NH    8
#define DK    128
#define DV    128
#define KCONV 4
#define SCALE 0.08838834764831845f   // 128^-0.5
#define EPS   1e-5f

// ---------------------------------------------------------------------------
// Static device scratch
// ---------------------------------------------------------------------------
__device__ float g_qb[S_LEN * HID];
__device__ float g_kb[S_LEN * HID];
__device__ float g_vb[S_LEN * HID];
__device__ float g_qc[S_LEN * HID];
__device__ float g_kc[S_LEN * HID];
__device__ float g_vc[S_LEN * HID];
__device__ float g_gb[S_LEN * HID];
__device__ float g_ob[S_LEN * HID];
__device__ float g_o2[S_LEN * HID];
__device__ float g_alpha[S_LEN * NH];
__device__ float g_beta [S_LEN * NH];

// ---------------------------------------------------------------------------
// SGEMM: C[M,N] = A[M,K] * B[N,K]^T. 128x128 tile, 8x8 microtile, double-buffer.
// blockIdx.z selects one of up to 4 (B, C) pairs.
// ---------------------------------------------------------------------------
__global__ __launch_bounds__(256, 2) void sgemm_tn4(const float* __restrict__ A,
                                                    const float* __restrict__ B0,
                                                    const float* __restrict__ B1,
                                                    const float* __restrict__ B2,
                                                    const float* __restrict__ B3,
                                                    float* __restrict__ C0,
                                                    float* __restrict__ C1,
                                                    float* __restrict__ C2,
                                                    float* __restrict__ C3,
                                                    int M, int N, int K) {
    const int z = blockIdx.z;
    const float* B = (z == 0) ? B0 : (z == 1) ? B1 : (z == 2) ? B2 : B3;
    float*       C = (z == 0) ? C0 : (z == 1) ? C1 : (z == 2) ? C2 : C3;

    __shared__ float As[2][8][128];
    __shared__ float Bs[2][8][128];

    const int tid = threadIdx.x;
    const int bm = blockIdx.y * 128;
    const int bn = blockIdx.x * 128;

    const int lr = tid >> 1;
    const int lc = (tid & 1) * 4;
    const int tx = tid & 15;
    const int ty = tid >> 4;

    float acc[8][8];
#pragma unroll
    for (int i = 0; i < 8; i++)
#pragma unroll
        for (int j = 0; j < 8; j++) acc[i][j] = 0.f;

    float4 av = *reinterpret_cast<const float4*>(&A[(size_t)(bm + lr) * K + lc]);
    float4 bv = *reinterpret_cast<const float4*>(&B[(size_t)(bn + lr) * K + lc]);
    As[0][lc + 0][lr] = av.x; As[0][lc + 1][lr] = av.y;
    As[0][lc + 2][lr] = av.z; As[0][lc + 3][lr] = av.w;
    Bs[0][lc + 0][lr] = bv.x; Bs[0][lc + 1][lr] = bv.y;
    Bs[0][lc + 2][lr] = bv.z; Bs[0][lc + 3][lr] = bv.w;
    __syncthreads();

    for (int kt = 0; kt < K; kt += 8) {
        const int cur = (kt >> 3) & 1;
        const int nxt = cur ^ 1;
        float4 an, bn4;
        const bool has_next = (kt + 8) < K;
        if (has_next) {
            an  = *reinterpret_cast<const float4*>(&A[(size_t)(bm + lr) * K + kt + 8 + lc]);
            bn4 = *reinterpret_cast<const float4*>(&B[(size_t)(bn + lr) * K + kt + 8 + lc]);
        }
#pragma unroll
        for (int kk = 0; kk < 8; kk++) {
            float4 a0 = *reinterpret_cast<const float4*>(&As[cur][kk][ty * 8]);
            float4 a1 = *reinterpret_cast<const float4*>(&As[cur][kk][ty * 8 + 4]);
            float4 b0 = *reinterpret_cast<const float4*>(&Bs[cur][kk][tx * 8]);
            float4 b1 = *reinterpret_cast<const float4*>(&Bs[cur][kk][tx * 8 + 4]);
            float ar[8] = {a0.x, a0.y, a0.z, a0.w, a1.x, a1.y, a1.z, a1.w};
            float br[8] = {b0.x, b0.y, b0.z, b0.w, b1.x, b1.y, b1.z, b1.w};
#pragma unroll
            for (int i = 0; i < 8; i++)
#pragma unroll
                for (int j = 0; j < 8; j++) acc[i][j] = fmaf(ar[i], br[j], acc[i][j]);
        }
        if (has_next) {
            As[nxt][lc + 0][lr] = an.x;  As[nxt][lc + 1][lr] = an.y;
            As[nxt][lc + 2][lr] = an.z;  As[nxt][lc + 3][lr] = an.w;
            Bs[nxt][lc + 0][lr] = bn4.x; Bs[nxt][lc + 1][lr] = bn4.y;
            Bs[nxt][lc + 2][lr] = bn4.z; Bs[nxt][lc + 3][lr] = bn4.w;
            __syncthreads();
        }
    }

#pragma unroll
    for (int i = 0; i < 8; i++) {
        const size_t row = (size_t)(bm + ty * 8 + i) * N + bn + tx * 8;
        *reinterpret_cast<float4*>(&C[row])     = make_float4(acc[i][0], acc[i][1], acc[i][2], acc[i][3]);
        *reinterpret_cast<float4*>(&C[row + 4]) = make_float4(acc[i][4], acc[i][5], acc[i][6], acc[i][7]);
    }
}

// ---------------------------------------------------------------------------
// alpha/beta projections
// ---------------------------------------------------------------------------
__global__ __launch_bounds__(256) void ab_kernel(const float* __restrict__ x,
                                                 const float* __restrict__ Wa,
                                                 const float* __restrict__ ba,
                                                 const float* __restrict__ Wb,
                                                 const float* __restrict__ bb,
                                                 float* __restrict__ alpha,
                                                 float* __restrict__ beta) {
    const int t = blockIdx.x;
    const int w = threadIdx.x >> 5;
    const int lane = threadIdx.x & 31;
    const float* xr = x + (size_t)t * HID;
    const float* war = Wa + (size_t)w * HID;
    const float* wbr = Wb + (size_t)w * HID;
    float sa = 0.f, sb = 0.f;
    for (int i = lane; i < HID; i += 32) {
        float xv = xr[i];
        sa = fmaf(xv, war[i], sa);
        sb = fmaf(xv, wbr[i], sb);
    }
#pragma unroll
    for (int off = 16; off > 0; off >>= 1) {
        sa += __shfl_down_sync(0xffffffffu, sa, off);
        sb += __shfl_down_sync(0xffffffffu, sb, off);
    }
    if (lane == 0) {
        alpha[t * NH + w] = 1.f / (1.f + expf(-(sa + ba[w])));
        beta [t * NH + w] = 1.f / (1.f + expf(-(sb + bb[w])));
    }
}

// ---------------------------------------------------------------------------
// Fused depthwise causal conv (K=4) + bias + SiLU for q/k/v.
// ---------------------------------------------------------------------------
__global__ __launch_bounds__(256) void conv_silu3(const float* __restrict__ inq,
                                                  const float* __restrict__ ink,
                                                  const float* __restrict__ inv,
                                                  const float* __restrict__ wq,
                                                  const float* __restrict__ bq,
                                                  const float* __restrict__ wk,
                                                  const float* __restrict__ bk,
                                                  const float* __restrict__ wv,
                                                  const float* __restrict__ bv,
                                                  float* __restrict__ outq,
                                                  float* __restrict__ outk,
                                                  float* __restrict__ outv) {
    const int z = blockIdx.y;
    const float* in  = (z == 0) ? inq : (z == 1) ? ink : inv;
    const float* w   = (z == 0) ? wq  : (z == 1) ? wk  : wv;
    const float* b   = (z == 0) ? bq  : (z == 1) ? bk  : bv;
    float*       out = (z == 0) ? outq: (z == 1) ? outk: outv;
    const float scale = (z == 1) ? SCALE : 1.0f;

    const int idx = blockIdx.x * 256 + threadIdx.x;
    const int t = idx >> 10;
    const int c = idx & 1023;
    float acc = b[c];
#pragma unroll
    for (int j = 0; j < KCONV; j++) {
        const int tt = t + j - (KCONV - 1);
        if (tt >= 0) acc = fmaf(in[((size_t)tt << 10) + c], w[c * KCONV + j], acc);
    }
    const float sil = acc / (1.f + expf(-acc));
    out[idx] = sil * scale;
}

// ---------------------------------------------------------------------------
// Gated DeltaNet recurrence v4 — lookahead-linearized, 3-phase load pipeline.
//
// Row-parallel. 8 lanes/row, 16 state floats/lane, 4 rows/warp.
// 64 blocks x 128 threads (1 warp/SMSP). 3 rotating register buffers for
// k/q/v/a/b => load-to-first-use distance = 2 steps (~400cyc) > L2 latency.
//
// Lookahead: dot_{t+1} = a_t*P + nb_t*R, P = s_{t-1}.k_{t+1}, R = k_t.k_{t+1}.
// ---------------------------------------------------------------------------
__global__ __launch_bounds__(128) void recurrence4(const float* __restrict__ q,
                                                   const float* __restrict__ k,
                                                   const float* __restrict__ v,
                                                   const float* __restrict__ alpha,
                                                   const float* __restrict__ beta,
                                                   float* __restrict__ o) {
    const int h  = blockIdx.x >> 3;            // head 0..7
    const int rg = blockIdx.x & 7;             // row group (16 rows)
    const int wid  = threadIdx.x >> 5;         // 0..3
    const int lane = threadIdx.x & 31;
    const int row = rg * 16 + wid * 4 + (lane >> 3);
    const int seg = lane & 7;
    const int hoff = h * DK;

    const float* kp = k + hoff + seg * 16;
    const float* qp = q + hoff + seg * 16;
    const float* vp = v + hoff + row;
    const float* ap = alpha + h;
    const float* bp = beta + h;
    float* op = o + hoff + row;

    float s[16];
#pragma unroll
    for (int j = 0; j < 16; j++) s[j] = 0.f;

    float k0[16], q0[16], k1[16], q1[16], k2[16], q2[16];
    float v0, a0, b0, v1, a1, b1, v2, a2, b2;

#define LOADSTEP(K_, Q_, V_, A_, B_, T_) {                                        \
    const int tc_ = ((T_) < S_LEN) ? (T_) : (S_LEN - 1);                          \
    const size_t off_ = (size_t)tc_ * HID;                                        \
    _Pragma("unroll")                                                             \
    for (int i_ = 0; i_ < 4; i_++) {                                              \
        float4 kv_ = __ldg(reinterpret_cast<const float4*>(kp + off_) + i_);      \
        float4 qv_ = __ldg(reinterpret_cast<const float4*>(qp + off_) + i_);      \
        K_[4*i_+0] = kv_.x; K_[4*i_+1] = kv_.y; K_[4*i_+2] = kv_.z; K_[4*i_+3] = kv_.w; \
        Q_[4*i_+0] = qv_.x; Q_[4*i_+1] = qv_.y; Q_[4*i_+2] = qv_.z; Q_[4*i_+3] = qv_.w; \
    }                                                                             \
    V_ = __ldg(vp + off_);                                                        \
    A_ = __ldg(ap + (size_t)tc_ * NH);                                            \
    B_ = __ldg(bp + (size_t)tc_ * NH);                                            \
}

#define RED8(x_) {                                                                \
    x_ += __shfl_xor_sync(0xffffffffu, x_, 1);                                    \
    x_ += __shfl_xor_sync(0xffffffffu, x_, 2);                                    \
    x_ += __shfl_xor_sync(0xffffffffu, x_, 4);                                    \
}

// One step. KC/QC/VC/AC/BC = step-t inputs, KN = step-(t+1) k.
// At end, reload the C buffers with step t+3 (consumed as KN at t+2).
#define STEP(KC, QC, VC, AC, BC, KN, T_) {                                        \
    const float nb = BC * (VC - dot);                                             \
    float P0=0.f,P1=0.f,P2=0.f,P3=0.f, R0=0.f,R1=0.f,R2=0.f,R3=0.f;               \
    _Pragma("unroll")                                                             \
    for (int j = 0; j < 16; j += 4) {                                             \
        P0 = fmaf(s[j+0], KN[j+0], P0);  R0 = fmaf(KC[j+0], KN[j+0], R0);         \
        P1 = fmaf(s[j+1], KN[j+1], P1);  R1 = fmaf(KC[j+1], KN[j+1], R1);         \
        P2 = fmaf(s[j+2], KN[j+2], P2);  R2 = fmaf(KC[j+2], KN[j+2], R2);         \
        P3 = fmaf(s[j+3], KN[j+3], P3);  R3 = fmaf(KC[j+3], KN[j+3], R3);         \
    }                                                                             \
    float P = (P0 + P1) + (P2 + P3);                                              \
    float R = (R0 + R1) + (R2 + R3);                                              \
    float o0=0.f,o1=0.f,o2=0.f,o3=0.f;                                            \
    _Pragma("unroll")                                                             \
    for (int j = 0; j < 16; j += 4) {                                             \
        float sn0 = fmaf(AC, s[j+0], nb * KC[j+0]);                               \
        float sn1 = fmaf(AC, s[j+1], nb * KC[j+1]);                               \
        float sn2 = fmaf(AC, s[j+2], nb * KC[j+2]);                               \
        float sn3 = fmaf(AC, s[j+3], nb * KC[j+3]);                               \
        s[j+0]=sn0; s[j+1]=sn1; s[j+2]=sn2; s[j+3]=sn3;                           \
        o0 = fmaf(sn0, QC[j+0], o0);  o1 = fmaf(sn1, QC[j+1], o1);                \
        o2 = fmaf(sn2, QC[j+2], o2);  o3 = fmaf(sn3, QC[j+3], o3);                \
    }                                                                             \
    float ov = (o0 + o1) + (o2 + o3);                                             \
    RED8(P); RED8(R); RED8(ov);                                                   \
    dot = fmaf(AC, P, nb * R);                                                    \
    if (seg == 0) op[(size_t)(T_) * HID] = ov;                                    \
    {                                                                             \
        const int tpf = ((T_) + 9 < S_LEN) ? (T_) + 9 : (S_LEN - 1);              \
        asm volatile("prefetch.global.L1 [%0];" :: "l"((const char*)(kp + (size_t)tpf * HID))); \
        asm volatile("prefetch.global.L1 [%0];" :: "l"((const char*)(qp + (size_t)tpf * HID))); \
        LOADSTEP(KC, QC, VC, AC, BC, (T_) + 3);                                   \
    }                                                                             \
}

    LOADSTEP(k0, q0, v0, a0, b0, 0);
    LOADSTEP(k1, q1, v1, a1, b1, 1);
    LOADSTEP(k2, q2, v2, a2, b2, 2);
    float dot = 0.f;   // s_{-1}.k_0 = 0

    // 2046 = 3*682; tail of 2 handled after the loop.
    for (int t = 0; t < 2046; t += 3) {
        STEP(k0, q0, v0, a0, b0, k1, t);
        STEP(k1, q1, v1, a1, b1, k2, t + 1);
        STEP(k2, q2, v2, a2, b2, k0, t + 2);
    }
    // t=2046: C=buf0 (holds 2046), N=buf1 (2047)
    STEP(k0, q0, v0, a0, b0, k1, 2046);
    // t=2047: C=buf1 (2047), N=buf2 (clamped; dot result unused)
    STEP(k1, q1, v1, a1, b1, k2, 2047);
#undef STEP
#undef RED8
#undef LOADSTEP
}

// ---------------------------------------------------------------------------
// LayerNorm over DV + sigmoid gate.
// ---------------------------------------------------------------------------
__global__ __launch_bounds__(128) void ln_gate(const float* __restrict__ o,
                                               const float* __restrict__ gb,
                                               const float* __restrict__ ln_g,
                                               const float* __restrict__ ln_b,
                                               float* __restrict__ out) {
    const int row = blockIdx.x;
    const int d = threadIdx.x;
    const size_t idx = (size_t)row * DV + d;
    const float val = o[idx];

    __shared__ float red[4], red2[4];
    float sum = val;
#pragma unroll
    for (int off = 16; off > 0; off >>= 1) sum += __shfl_down_sync(0xffffffffu, sum, off);
    if ((d & 31) == 0) red[d >> 5] = sum;
    __syncthreads();
    const float mu = (red[0] + red[1] + red[2] + red[3]) * (1.f / DV);
    const float diff = val - mu;
    float sq = diff * diff;
#pragma unroll
    for (int off = 16; off > 0; off >>= 1) sq += __shfl_down_sync(0xffffffffu, sq, off);
    if ((d & 31) == 0) red2[d >> 5] = sq;
    __syncthreads();
    const float var = (red2[0] + red2[1] + red2[2] + red2[3]) * (1.f / DV);
    const float y = diff * rsqrtf(var + EPS) * ln_g[d] + ln_b[d];
    const float gate = 1.f / (1.f + expf(-gb[idx]));
    out[idx] = y * gate;
}

// ---------------------------------------------------------------------------
// Launch
// ---------------------------------------------------------------------------
extern "C" void kernel_launch(void* const* d_in, const int* in_sizes, int n_in,
                              void* d_out, int out_size) {
    const float* x       = (const float*)d_in[0];
    const float* Wq      = (const float*)d_in[1];
    const float* Wk      = (const float*)d_in[2];
    const float* Wv      = (const float*)d_in[3];
    const float* cqw     = (const float*)d_in[4];
    const float* cqb     = (const float*)d_in[5];
    const float* ckw     = (const float*)d_in[6];
    const float* ckb     = (const float*)d_in[7];
    const float* cvw     = (const float*)d_in[8];
    const float* cvb     = (const float*)d_in[9];
    const float* Wa      = (const float*)d_in[10];
    const float* ba      = (const float*)d_in[11];
    const float* Wb      = (const float*)d_in[12];
    const float* bb      = (const float*)d_in[13];
    const float* Wg      = (const float*)d_in[14];
    const float* ln_g    = (const float*)d_in[15];
    const float* ln_b    = (const float*)d_in[16];
    const float* Wo      = (const float*)d_in[17];
    float* out = (float*)d_out;

    float *qb, *kb, *vb, *qc, *kc, *vc, *gb, *ob, *o2, *al, *be;
    cudaGetSymbolAddress((void**)&qb, g_qb);
    cudaGetSymbolAddress((void**)&kb, g_kb);
    cudaGetSymbolAddress((void**)&vb, g_vb);
    cudaGetSymbolAddress((void**)&qc, g_qc);
    cudaGetSymbolAddress((void**)&kc, g_kc);
    cudaGetSymbolAddress((void**)&vc, g_vc);
    cudaGetSymbolAddress((void**)&gb, g_gb);
    cudaGetSymbolAddress((void**)&ob, g_ob);
    cudaGetSymbolAddress((void**)&o2, g_o2);
    cudaGetSymbolAddress((void**)&al, g_alpha);
    cudaGetSymbolAddress((void**)&be, g_beta);

    dim3 g4(HID / 128, S_LEN / 128, 4);
    sgemm_tn4<<<g4, 256>>>(x, Wq, Wk, Wv, Wg, qb, kb, vb, gb, S_LEN, HID, HID);

    ab_kernel<<<S_LEN, 256>>>(x, Wa, ba, Wb, bb, al, be);

    dim3 gc(S_LEN * HID / 256, 3);
    conv_silu3<<<gc, 256>>>(qb, kb, vb, cqw, cqb, ckw, ckb, cvw, cvb, qc, kc, vc);

    recurrence4<<<64, 128>>>(qc, kc, vc, al, be, ob);

    ln_gate<<<S_LEN * NH, 128>>>(ob, gb, ln_g, ln_b, o2);

    dim3 g1(HID / 128, S_LEN / 128, 1);
    sgemm_tn4<<<g1, 256>>>(o2, Wo, Wo, Wo, Wo, out, out, out, out, S_LEN, HID, HID);
}

// round 9
// speedup vs baseline: 4.6492x; 1.2276x over previous
#include <cuda_runtime.h>
#include <cuda_bf16.h>
#include <math.h>
#include <stdint.h>

#define S_LEN 2048
#define HID   1024
#define NH    8
#define DK    128
#define DV    128
#define KCONV 4
#define SCALE 0.08838834764831845f   // 128^-0.5
#define EPS   1e-5f

// ---------------------------------------------------------------------------
// Static device scratch
// ---------------------------------------------------------------------------
__device__ float g_qb[S_LEN * HID];
__device__ float g_kb[S_LEN * HID];
__device__ float g_vb[S_LEN * HID];
__device__ float g_qc[S_LEN * HID];
__device__ float g_kc[S_LEN * HID];
__device__ float g_vc[S_LEN * HID];
__device__ float g_gb[S_LEN * HID];
__device__ float g_ob[S_LEN * HID];
__device__ float g_o2[S_LEN * HID];
__device__ float g_alpha[S_LEN * NH];
__device__ float g_beta [S_LEN * NH];

// ---------------------------------------------------------------------------
// SGEMM: C[M,N] = A[M,K] * B[N,K]^T. 128x128 tile, 8x8 microtile, double-buffer.
// ---------------------------------------------------------------------------
__global__ __launch_bounds__(256, 2) void sgemm_tn4(const float* __restrict__ A,
                                                    const float* __restrict__ B0,
                                                    const float* __restrict__ B1,
                                                    const float* __restrict__ B2,
                                                    const float* __restrict__ B3,
                                                    float* __restrict__ C0,
                                                    float* __restrict__ C1,
                                                    float* __restrict__ C2,
                                                    float* __restrict__ C3,
                                                    int M, int N, int K) {
    const int z = blockIdx.z;
    const float* B = (z == 0) ? B0 : (z == 1) ? B1 : (z == 2) ? B2 : B3;
    float*       C = (z == 0) ? C0 : (z == 1) ? C1 : (z == 2) ? C2 : C3;

    __shared__ float As[2][8][128];
    __shared__ float Bs[2][8][128];

    const int tid = threadIdx.x;
    const int bm = blockIdx.y * 128;
    const int bn = blockIdx.x * 128;

    const int lr = tid >> 1;
    const int lc = (tid & 1) * 4;
    const int tx = tid & 15;
    const int ty = tid >> 4;

    float acc[8][8];
#pragma unroll
    for (int i = 0; i < 8; i++)
#pragma unroll
        for (int j = 0; j < 8; j++) acc[i][j] = 0.f;

    float4 av = *reinterpret_cast<const float4*>(&A[(size_t)(bm + lr) * K + lc]);
    float4 bv = *reinterpret_cast<const float4*>(&B[(size_t)(bn + lr) * K + lc]);
    As[0][lc + 0][lr] = av.x; As[0][lc + 1][lr] = av.y;
    As[0][lc + 2][lr] = av.z; As[0][lc + 3][lr] = av.w;
    Bs[0][lc + 0][lr] = bv.x; Bs[0][lc + 1][lr] = bv.y;
    Bs[0][lc + 2][lr] = bv.z; Bs[0][lc + 3][lr] = bv.w;
    __syncthreads();

    for (int kt = 0; kt < K; kt += 8) {
        const int cur = (kt >> 3) & 1;
        const int nxt = cur ^ 1;
        float4 an, bn4;
        const bool has_next = (kt + 8) < K;
        if (has_next) {
            an  = *reinterpret_cast<const float4*>(&A[(size_t)(bm + lr) * K + kt + 8 + lc]);
            bn4 = *reinterpret_cast<const float4*>(&B[(size_t)(bn + lr) * K + kt + 8 + lc]);
        }
#pragma unroll
        for (int kk = 0; kk < 8; kk++) {
            float4 a0 = *reinterpret_cast<const float4*>(&As[cur][kk][ty * 8]);
            float4 a1 = *reinterpret_cast<const float4*>(&As[cur][kk][ty * 8 + 4]);
            float4 b0 = *reinterpret_cast<const float4*>(&Bs[cur][kk][tx * 8]);
            float4 b1 = *reinterpret_cast<const float4*>(&Bs[cur][kk][tx * 8 + 4]);
            float ar[8] = {a0.x, a0.y, a0.z, a0.w, a1.x, a1.y, a1.z, a1.w};
            float br[8] = {b0.x, b0.y, b0.z, b0.w, b1.x, b1.y, b1.z, b1.w};
#pragma unroll
            for (int i = 0; i < 8; i++)
#pragma unroll
                for (int j = 0; j < 8; j++) acc[i][j] = fmaf(ar[i], br[j], acc[i][j]);
        }
        if (has_next) {
            As[nxt][lc + 0][lr] = an.x;  As[nxt][lc + 1][lr] = an.y;
            As[nxt][lc + 2][lr] = an.z;  As[nxt][lc + 3][lr] = an.w;
            Bs[nxt][lc + 0][lr] = bn4.x; Bs[nxt][lc + 1][lr] = bn4.y;
            Bs[nxt][lc + 2][lr] = bn4.z; Bs[nxt][lc + 3][lr] = bn4.w;
            __syncthreads();
        }
    }

#pragma unroll
    for (int i = 0; i < 8; i++) {
        const size_t row = (size_t)(bm + ty * 8 + i) * N + bn + tx * 8;
        *reinterpret_cast<float4*>(&C[row])     = make_float4(acc[i][0], acc[i][1], acc[i][2], acc[i][3]);
        *reinterpret_cast<float4*>(&C[row + 4]) = make_float4(acc[i][4], acc[i][5], acc[i][6], acc[i][7]);
    }
}

// ---------------------------------------------------------------------------
// alpha/beta projections
// ---------------------------------------------------------------------------
__global__ __launch_bounds__(256) void ab_kernel(const float* __restrict__ x,
                                                 const float* __restrict__ Wa,
                                                 const float* __restrict__ ba,
                                                 const float* __restrict__ Wb,
                                                 const float* __restrict__ bb,
                                                 float* __restrict__ alpha,
                                                 float* __restrict__ beta) {
    const int t = blockIdx.x;
    const int w = threadIdx.x >> 5;
    const int lane = threadIdx.x & 31;
    const float* xr = x + (size_t)t * HID;
    const float* war = Wa + (size_t)w * HID;
    const float* wbr = Wb + (size_t)w * HID;
    float sa = 0.f, sb = 0.f;
    for (int i = lane; i < HID; i += 32) {
        float xv = xr[i];
        sa = fmaf(xv, war[i], sa);
        sb = fmaf(xv, wbr[i], sb);
    }
#pragma unroll
    for (int off = 16; off > 0; off >>= 1) {
        sa += __shfl_down_sync(0xffffffffu, sa, off);
        sb += __shfl_down_sync(0xffffffffu, sb, off);
    }
    if (lane == 0) {
        alpha[t * NH + w] = 1.f / (1.f + expf(-(sa + ba[w])));
        beta [t * NH + w] = 1.f / (1.f + expf(-(sb + bb[w])));
    }
}

// ---------------------------------------------------------------------------
// Fused depthwise causal conv (K=4) + bias + SiLU for q/k/v.
// ---------------------------------------------------------------------------
__global__ __launch_bounds__(256) void conv_silu3(const float* __restrict__ inq,
                                                  const float* __restrict__ ink,
                                                  const float* __restrict__ inv,
                                                  const float* __restrict__ wq,
                                                  const float* __restrict__ bq,
                                                  const float* __restrict__ wk,
                                                  const float* __restrict__ bk,
                                                  const float* __restrict__ wv,
                                                  const float* __restrict__ bv,
                                                  float* __restrict__ outq,
                                                  float* __restrict__ outk,
                                                  float* __restrict__ outv) {
    const int z = blockIdx.y;
    const float* in  = (z == 0) ? inq : (z == 1) ? ink : inv;
    const float* w   = (z == 0) ? wq  : (z == 1) ? wk  : wv;
    const float* b   = (z == 0) ? bq  : (z == 1) ? bk  : bv;
    float*       out = (z == 0) ? outq: (z == 1) ? outk: outv;
    const float scale = (z == 1) ? SCALE : 1.0f;

    const int idx = blockIdx.x * 256 + threadIdx.x;
    const int t = idx >> 10;
    const int c = idx & 1023;
    float acc = b[c];
#pragma unroll
    for (int j = 0; j < KCONV; j++) {
        const int tt = t + j - (KCONV - 1);
        if (tt >= 0) acc = fmaf(in[((size_t)tt << 10) + c], w[c * KCONV + j], acc);
    }
    const float sil = acc / (1.f + expf(-acc));
    out[idx] = sil * scale;
}

// ---------------------------------------------------------------------------
// Gated DeltaNet recurrence v5 — cp.async smem ring, structural pipeline.
//
// 128 blocks (8 heads x 16 row-groups of 8 rows), 128 threads (4 warps).
// Each warp handles 2 rows; 16 lanes/row, 8 state floats/lane.
// 8-stage cp.async ring for k/q/v/alpha/beta: load-to-use distance = 7 steps,
// enforced by cp.async.wait_group (ptxas cannot sink LDGSTS to its consumer).
// Lookahead keeps the serial chain at ~16cyc: dot_{t+1} = a*P + nb*R with
//   P = s_{t-1}.k_{t+1}, R = k_t.k_{t+1}.
// ---------------------------------------------------------------------------
#define NST 8

#define CPA16(dst, src) asm volatile("cp.async.ca.shared.global [%0], [%1], 16;\n" :: "r"(dst), "l"(src))
#define CPA4(dst, src)  asm volatile("cp.async.ca.shared.global [%0], [%1], 4;\n"  :: "r"(dst), "l"(src))
#define CPCOMMIT()      asm volatile("cp.async.commit_group;\n" ::: "memory")
#define CPWAIT(n)       asm volatile("cp.async.wait_group %0;\n" :: "n"(n) : "memory")

__global__ __launch_bounds__(128) void recurrence5(const float* __restrict__ q,
                                                   const float* __restrict__ k,
                                                   const float* __restrict__ v,
                                                   const float* __restrict__ alpha,
                                                   const float* __restrict__ beta,
                                                   float* __restrict__ o) {
    const int h  = blockIdx.x >> 4;            // head 0..7
    const int rg = blockIdx.x & 15;            // row group (8 rows)
    const int tid = threadIdx.x;
    const int wid  = tid >> 5;                 // 0..3
    const int lane = tid & 31;
    const int rloc = wid * 2 + (lane >> 4);    // 0..7 row within block
    const int row  = rg * 8 + rloc;            // 0..127
    const int l16  = lane & 15;                // 8-float segment index
    const int hoff = h * DK;

    __shared__ float sk[NST][128];
    __shared__ float sq[NST][128];
    __shared__ float sv[NST][8];
    __shared__ float sab[NST][2];

    // ---- per-thread cp.async role ----
    const char*  gsrc = nullptr;
    unsigned int sdst = 0;
    int          sstride = 0;                  // bytes per stage
    size_t       gstride = (size_t)HID * 4;    // bytes per timestep
    int          csize = 16;
    if (tid < 32) {
        gsrc = (const char*)(k + hoff + tid * 4);
        sdst = (unsigned int)__cvta_generic_to_shared(&sk[0][tid * 4]);
        sstride = 128 * 4;
    } else if (tid < 64) {
        gsrc = (const char*)(q + hoff + (tid - 32) * 4);
        sdst = (unsigned int)__cvta_generic_to_shared(&sq[0][(tid - 32) * 4]);
        sstride = 128 * 4;
    } else if (tid < 66) {
        gsrc = (const char*)(v + hoff + rg * 8 + (tid - 64) * 4);
        sdst = (unsigned int)__cvta_generic_to_shared(&sv[0][(tid - 64) * 4]);
        sstride = 8 * 4;
    } else if (tid == 66) {
        gsrc = (const char*)(alpha + h);
        sdst = (unsigned int)__cvta_generic_to_shared(&sab[0][0]);
        sstride = 2 * 4; gstride = (size_t)NH * 4; csize = 4;
    } else if (tid == 67) {
        gsrc = (const char*)(beta + h);
        sdst = (unsigned int)__cvta_generic_to_shared(&sab[0][1]);
        sstride = 2 * 4; gstride = (size_t)NH * 4; csize = 4;
    }

#define ISSUE_STAGE(SLOT_, TG_) {                                             \
    if (gsrc) {                                                               \
        const int tc_ = ((TG_) < S_LEN) ? (TG_) : (S_LEN - 1);                \
        const char* p_ = gsrc + (size_t)tc_ * gstride;                        \
        const unsigned int d_ = sdst + (SLOT_) * sstride;                     \
        if (csize == 16) { CPA16(d_, p_); } else { CPA4(d_, p_); }            \
    }                                                                         \
    CPCOMMIT();                                                               \
}

    // prologue: stages 0..NST-2 in flight (7 groups)
#pragma unroll
    for (int i = 0; i < NST - 1; i++) ISSUE_STAGE(i, i);

    float s[8];
#pragma unroll
    for (int j = 0; j < 8; j++) s[j] = 0.f;
    float dot = 0.f;

    float* op = o + hoff + row;
    const int kbase = l16 * 8;

#define RED16(x_) {                                                           \
    x_ += __shfl_xor_sync(0xffffffffu, x_, 1);                                \
    x_ += __shfl_xor_sync(0xffffffffu, x_, 2);                                \
    x_ += __shfl_xor_sync(0xffffffffu, x_, 4);                                \
    x_ += __shfl_xor_sync(0xffffffffu, x_, 8);                                \
}

    for (int t = 0; t < S_LEN; t++) {
        const int st  = t & (NST - 1);
        const int stn = (t + 1) & (NST - 1);

        CPWAIT(5);              // stages t and t+1 complete (per-thread queues match)
        __syncthreads();        // warp0-2's smem writes visible to all

        // smem -> regs (LDS, short latency)
        float kk[8], kn[8], qq[8];
        {
            float4 a0 = *reinterpret_cast<const float4*>(&sk[st][kbase]);
            float4 a1 = *reinterpret_cast<const float4*>(&sk[st][kbase + 4]);
            kk[0]=a0.x; kk[1]=a0.y; kk[2]=a0.z; kk[3]=a0.w;
            kk[4]=a1.x; kk[5]=a1.y; kk[6]=a1.z; kk[7]=a1.w;
            float4 b0 = *reinterpret_cast<const float4*>(&sk[stn][kbase]);
            float4 b1 = *reinterpret_cast<const float4*>(&sk[stn][kbase + 4]);
            kn[0]=b0.x; kn[1]=b0.y; kn[2]=b0.z; kn[3]=b0.w;
            kn[4]=b1.x; kn[5]=b1.y; kn[6]=b1.z; kn[7]=b1.w;
            float4 c0 = *reinterpret_cast<const float4*>(&sq[st][kbase]);
            float4 c1 = *reinterpret_cast<const float4*>(&sq[st][kbase + 4]);
            qq[0]=c0.x; qq[1]=c0.y; qq[2]=c0.z; qq[3]=c0.w;
            qq[4]=c1.x; qq[5]=c1.y; qq[6]=c1.z; qq[7]=c1.w;
        }
        const float vv = sv[st][rloc];
        const float aa = sab[st][0];
        const float bb = sab[st][1];

        const float nb = bb * (vv - dot);       // serial scalar chain

        // P = s_{t-1}.k_{t+1}, R = k_t.k_{t+1}  (off-chain, reduced below)
        float P0=0.f,P1=0.f,P2=0.f,P3=0.f, R0=0.f,R1=0.f,R2=0.f,R3=0.f;
#pragma unroll
        for (int j = 0; j < 8; j += 4) {
            P0 = fmaf(s[j+0], kn[j+0], P0);  R0 = fmaf(kk[j+0], kn[j+0], R0);
            P1 = fmaf(s[j+1], kn[j+1], P1);  R1 = fmaf(kk[j+1], kn[j+1], R1);
            P2 = fmaf(s[j+2], kn[j+2], P2);  R2 = fmaf(kk[j+2], kn[j+2], R2);
            P3 = fmaf(s[j+3], kn[j+3], P3);  R3 = fmaf(kk[j+3], kn[j+3], R3);
        }
        float P = (P0 + P1) + (P2 + P3);
        float R = (R0 + R1) + (R2 + R3);

        // state update + output partials
        float o0=0.f,o1=0.f,o2=0.f,o3=0.f;
#pragma unroll
        for (int j = 0; j < 8; j += 4) {
            float sn0 = fmaf(aa, s[j+0], nb * kk[j+0]);
            float sn1 = fmaf(aa, s[j+1], nb * kk[j+1]);
            float sn2 = fmaf(aa, s[j+2], nb * kk[j+2]);
            float sn3 = fmaf(aa, s[j+3], nb * kk[j+3]);
            s[j+0]=sn0; s[j+1]=sn1; s[j+2]=sn2; s[j+3]=sn3;
            o0 = fmaf(sn0, qq[j+0], o0);  o1 = fmaf(sn1, qq[j+1], o1);
            o2 = fmaf(sn2, qq[j+2], o2);  o3 = fmaf(sn3, qq[j+3], o3);
        }
        float ov = (o0 + o1) + (o2 + o3);

        RED16(P); RED16(R); RED16(ov);
        dot = fmaf(aa, P, nb * R);

        if (l16 == 0) op[(size_t)t * HID] = ov;

        // refill: data for step t+NST-1 into slot (t+NST-1)%NST (= slot t-1)
        ISSUE_STAGE((t + NST - 1) & (NST - 1), t + NST - 1);
    }
#undef RED16
#undef ISSUE_STAGE
}

// ---------------------------------------------------------------------------
// LayerNorm over DV + sigmoid gate.
// ---------------------------------------------------------------------------
__global__ __launch_bounds__(128) void ln_gate(const float* __restrict__ o,
                                               const float* __restrict__ gb,
                                               const float* __restrict__ ln_g,
                                               const float* __restrict__ ln_b,
                                               float* __restrict__ out) {
    const int row = blockIdx.x;
    const int d = threadIdx.x;
    const size_t idx = (size_t)row * DV + d;
    const float val = o[idx];

    __shared__ float red[4], red2[4];
    float sum = val;
#pragma unroll
    for (int off = 16; off > 0; off >>= 1) sum += __shfl_down_sync(0xffffffffu, sum, off);
    if ((d & 31) == 0) red[d >> 5] = sum;
    __syncthreads();
    const float mu = (red[0] + red[1] + red[2] + red[3]) * (1.f / DV);
    const float diff = val - mu;
    float sq = diff * diff;
#pragma unroll
    for (int off = 16; off > 0; off >>= 1) sq += __shfl_down_sync(0xffffffffu, sq, off);
    if ((d & 31) == 0) red2[d >> 5] = sq;
    __syncthreads();
    const float var = (red2[0] + red2[1] + red2[2] + red2[3]) * (1.f / DV);
    const float y = diff * rsqrtf(var + EPS) * ln_g[d] + ln_b[d];
    const float gate = 1.f / (1.f + expf(-gb[idx]));
    out[idx] = y * gate;
}

// ---------------------------------------------------------------------------
// Launch
// ---------------------------------------------------------------------------
extern "C" void kernel_launch(void* const* d_in, const int* in_sizes, int n_in,
                              void* d_out, int out_size) {
    const float* x       = (const float*)d_in[0];
    const float* Wq      = (const float*)d_in[1];
    const float* Wk      = (const float*)d_in[2];
    const float* Wv      = (const float*)d_in[3];
    const float* cqw     = (const float*)d_in[4];
    const float* cqb     = (const float*)d_in[5];
    const float* ckw     = (const float*)d_in[6];
    const float* ckb     = (const float*)d_in[7];
    const float* cvw     = (const float*)d_in[8];
    const float* cvb     = (const float*)d_in[9];
    const float* Wa      = (const float*)d_in[10];
    const float* ba      = (const float*)d_in[11];
    const float* Wb      = (const float*)d_in[12];
    const float* bb      = (const float*)d_in[13];
    const float* Wg      = (const float*)d_in[14];
    const float* ln_g    = (const float*)d_in[15];
    const float* ln_b    = (const float*)d_in[16];
    const float* Wo      = (const float*)d_in[17];
    float* out = (float*)d_out;

    float *qb, *kb, *vb, *qc, *kc, *vc, *gb, *ob, *o2, *al, *be;
    cudaGetSymbolAddress((void**)&qb, g_qb);
    cudaGetSymbolAddress((void**)&kb, g_kb);
    cudaGetSymbolAddress((void**)&vb, g_vb);
    cudaGetSymbolAddress((void**)&qc, g_qc);
    cudaGetSymbolAddress((void**)&kc, g_kc);
    cudaGetSymbolAddress((void**)&vc, g_vc);
    cudaGetSymbolAddress((void**)&gb, g_gb);
    cudaGetSymbolAddress((void**)&ob, g_ob);
    cudaGetSymbolAddress((void**)&o2, g_o2);
    cudaGetSymbolAddress((void**)&al, g_alpha);
    cudaGetSymbolAddress((void**)&be, g_beta);

    dim3 g4(HID / 128, S_LEN / 128, 4);
    sgemm_tn4<<<g4, 256>>>(x, Wq, Wk, Wv, Wg, qb, kb, vb, gb, S_LEN, HID, HID);

    ab_kernel<<<S_LEN, 256>>>(x, Wa, ba, Wb, bb, al, be);

    dim3 gc(S_LEN * HID / 256, 3);
    conv_silu3<<<gc, 256>>>(qb, kb, vb, cqw, cqb, ckw, ckb, cvw, cvb, qc, kc, vc);

    recurrence5<<<128, 128>>>(qc, kc, vc, al, be, ob);

    ln_gate<<<S_LEN * NH, 128>>>(ob, gb, ln_g, ln_b, o2);

    dim3 g1(HID / 128, S_LEN / 128, 1);
    sgemm_tn4<<<g1, 256>>>(o2, Wo, Wo, Wo, Wo, out, out, out, out, S_LEN, HID, HID);
}